// round 17
// baseline (speedup 1.0000x reference)
#include <cuda_runtime.h>
#include <cuda_fp16.h>

#define NPTS 16384
#define KSUB 16
#define WD   256
#define TWF  0.2f
#define PI_F 3.14159265358979f

#define A_STRIDE 264            // halves per A row (33x16B: ldmatrix conflict-free)
#define W_STRIDE 40             // halves per W row (5x16B: ldmatrix conflict-free)
#define WBUF_HALVES (256 * W_STRIDE)
#define WBUF_BYTES  (WBUF_HALVES * 2)

// smem byte offsets
#define B_A    0                // 128*264*2 = 67584
#define B_W    67584            // 4 * 20480 = 81920
#define B_XN   149504           // 256 f32
#define B_WN   150528           // 128 f32
#define B_IDX  151040           // 128 i32
#define B_BIAS 151552           // 512 f32
#define B_W3   153600           // 256 f32
#define SMEM_BYTES 154624

#define NTHR 512

__device__ int    g_count[KSUB];
__device__ int    g_idx[KSUB][NPTS];
__device__ float  g_wn[KSUB][NPTS];
// fp16 n-major weights: [2][16][chunk 8][n 256][k 32]
__device__ __half g_WTh[2 * KSUB * WD * WD];

__device__ __forceinline__ float ftanh(float x) {
    float e = __expf(-2.0f * x);
    return __fdividef(2.0f, 1.0f + e) - 1.0f;
}

// transpose one 32k x 256n chunk per block -> n-major fp16. 256 blocks x 256 thr.
__global__ void prep_kernel(const float* __restrict__ W1, const float* __restrict__ W2) {
    __shared__ __half tile[256][40];
    int b = blockIdx.x;
    int l = b >> 7, ks = (b >> 3) & 15, ch = b & 7;
    const float* src = (l ? W2 : W1) + ks * WD * WD + ch * 32 * WD;
    __half* dst = g_WTh + (size_t)((l * KSUB + ks) * 8 + ch) * 8192;
    int tid = threadIdx.x;
#pragma unroll
    for (int i = 0; i < 32; ++i)
        tile[tid][i] = __float2half_rn(src[i * WD + tid]);
    __syncthreads();
    uint4* gout = (uint4*)dst;
#pragma unroll
    for (int q = 0; q < 4; ++q) {
        int f = q * 256 + tid;
        int v = f >> 2, qq = f & 3;
        gout[f] = *(uint4*)&tile[v][qq * 8];
    }
    if (b == 0 && tid < KSUB) g_count[tid] = 0;
}

__global__ void window_kernel(const float* __restrict__ x,
                              const float* __restrict__ xmins,
                              const float* __restrict__ xmaxs,
                              float* __restrict__ out) {
    int n = blockIdx.x * blockDim.x + threadIdx.x;
    out[n] = 0.0f;
    float x0 = x[2 * n], x1 = x[2 * n + 1];
    float wr[KSUB], s = 0.0f;
#pragma unroll
    for (int k = 0; k < KSUB; ++k) {
        float tl0 = fminf(fmaxf((x0 - (xmins[2 * k] - TWF)) * 2.5f, 0.f), 1.f);
        float tr0 = fminf(fmaxf(((xmaxs[2 * k] + TWF) - x0) * 2.5f, 0.f), 1.f);
        float tl1 = fminf(fmaxf((x1 - (xmins[2 * k + 1] - TWF)) * 2.5f, 0.f), 1.f);
        float tr1 = fminf(fmaxf(((xmaxs[2 * k + 1] + TWF) - x1) * 2.5f, 0.f), 1.f);
        float f0 = 0.25f * (1.f - cosf(PI_F * tl0)) * (1.f - cosf(PI_F * tr0));
        float f1 = 0.25f * (1.f - cosf(PI_F * tl1)) * (1.f - cosf(PI_F * tr1));
        wr[k] = f0 * f1; s += wr[k];
    }
    float inv = 1.0f / (s + 1e-9f);
    int lane = threadIdx.x & 31;
#pragma unroll
    for (int k = 0; k < KSUB; ++k) {
        g_wn[k][n] = wr[k] * inv;
        bool act = (wr[k] > 0.0f);
        unsigned m = __ballot_sync(0xffffffffu, act);
        int base = 0;
        if (lane == 0 && m) base = atomicAdd(&g_count[k], __popc(m));
        base = __shfl_sync(0xffffffffu, base, 0);
        if (act) g_idx[k][base + __popc(m & ((1u << lane) - 1u))] = n;
    }
}

// stage one fp16 chunk [256 n x 32 k] = 16KB (512 threads: 2 x 16B each)
__device__ __forceinline__ void stage_chunk16(const uint4* __restrict__ src,
                                              __half* dstbase, int tid) {
#pragma unroll
    for (int q = 0; q < 2; ++q) {
        int f = q * NTHR + tid;
        int n = f >> 2, qq = f & 3;
        unsigned dst = (unsigned)__cvta_generic_to_shared(dstbase + n * W_STRIDE + qq * 8);
        asm volatile("cp.async.cg.shared.global [%0], [%1], 16;"
                     :: "r"(dst), "l"(src + f) : "memory");
    }
    asm volatile("cp.async.commit_group;" ::: "memory");
}

#define LDM_X4(r0, r1, r2, r3, addr) \
    asm volatile("ldmatrix.sync.aligned.m8n8.x4.shared.b16 {%0,%1,%2,%3}, [%4];" \
        : "=r"(r0), "=r"(r1), "=r"(r2), "=r"(r3) : "r"(addr))
// fp16-accumulator HMMA: D(f16x2 pair) = A*B + D
#define HMMA16(h0, h1, a0, a1, a2, a3, b0, b1) \
    asm volatile("mma.sync.aligned.m16n8k16.row.col.f16.f16.f16.f16 " \
        "{%0,%1}, {%2,%3,%4,%5}, {%6,%7}, {%0,%1};" \
        : "+r"(h0), "+r"(h1) \
        : "r"(a0), "r"(a1), "r"(a2), "r"(a3), "r"(b0), "r"(b1))

__global__ void __launch_bounds__(NTHR, 1)
mlp_kernel(const float* __restrict__ x,
           const float* __restrict__ W0, const float* __restrict__ b0,
           const float* __restrict__ b1, const float* __restrict__ b2,
           const float* __restrict__ W3, const float* __restrict__ b3,
           const float* __restrict__ xmins, const float* __restrict__ xmaxs,
           float* __restrict__ out) {
    extern __shared__ char smc[];
    int k = blockIdx.y, cnt = g_count[k], p0 = blockIdx.x * 128;
    if (p0 >= cnt) return;
    int npts = min(128, cnt - p0);
    int tid = threadIdx.x, wid = tid >> 5, lane = tid & 31;

    __half* A  = (__half*)(smc + B_A);
    __half* Wb = (__half*)(smc + B_W);
    float* sxn = (float*)(smc + B_XN);
    float* swn = (float*)(smc + B_WN);
    int* sidx  = (int*)(smc + B_IDX);
    float* sbias = (float*)(smc + B_BIAS);
    float* sw3 = (float*)(smc + B_W3);

    const __half* wsrc = g_WTh + (size_t)k * WD * WD;
    stage_chunk16((const uint4*)(wsrc), Wb, tid);
    stage_chunk16((const uint4*)(wsrc + 8192), Wb + WBUF_HALVES, tid);
    stage_chunk16((const uint4*)(wsrc + 16384), Wb + 2 * WBUF_HALVES, tid);

    if (tid < 128) {
        int i = g_idx[k][p0 + ((tid < npts) ? tid : (npts - 1))];
        sidx[tid] = i;
        float mn0 = xmins[2 * k], mn1 = xmins[2 * k + 1];
        float mx0 = xmaxs[2 * k], mx1 = xmaxs[2 * k + 1];
        float c0 = 0.5f * (mn0 + mx0), c1 = 0.5f * (mn1 + mx1);
        float s0 = fmaxf(0.5f * (mx0 - mn0), 1e-9f);
        float s1 = fmaxf(0.5f * (mx1 - mn1), 1e-9f);
        sxn[2 * tid] = (x[2 * i] - c0) / s0;
        sxn[2 * tid + 1] = (x[2 * i + 1] - c1) / s1;
        swn[tid] = g_wn[k][i];
    } else if (tid < 384) {
        int t2 = tid - 128;
        if (t2 < 256) sbias[t2] = b1[k * WD + t2];
    } else {
        int t2 = tid - 384;
        sbias[256 + t2] = b2[k * WD + t2];
        sbias[384 + t2] = b2[k * WD + 128 + t2];
    }
    if (tid < 256) sw3[tid] = W3[k * WD + tid];
    float b3k = b3[k];
    __syncthreads();

    // layer 0
    {
        const float* W0k = W0 + k * 2 * WD;
        int c2 = tid & 127, pg = tid >> 7;
        int v0 = 2 * c2;
        float wa0 = W0k[v0], wb0v = W0k[WD + v0];
        float wa1 = W0k[v0 + 1], wb1v = W0k[WD + v0 + 1];
        float ba = b0[k * WD + v0], bbv = b0[k * WD + v0 + 1];
        __half2* Arow = (__half2*)(A) + c2;
#pragma unroll 4
        for (int pp = 0; pp < 32; ++pp) {
            int p = pg * 32 + pp;
            float xa = sxn[2 * p], xb = sxn[2 * p + 1];
            float u0 = ftanh(fmaf(xa, wa0, fmaf(xb, wb0v, ba)));
            float u1 = ftanh(fmaf(xa, wa1, fmaf(xb, wb1v, bbv)));
            Arow[p * (A_STRIDE / 2)] = __floats2half2_rn(u0, u1);
        }
    }

    int N0 = (wid & 3) * 64, M0 = (wid >> 2) * 32;
    unsigned baseA = (unsigned)__cvta_generic_to_shared(A);
    unsigned baseW = (unsigned)__cvta_generic_to_shared(Wb);
    int l7 = lane & 7, lb3 = (lane >> 3) & 1, lb4 = (lane >> 4) & 1;
    unsigned offA_row = (unsigned)((lb3 * 8 + l7) * A_STRIDE + lb4 * 8) * 2u;
    unsigned offB_row = (unsigned)((lb4 * 8 + l7) * W_STRIDE + lb3 * 8) * 2u;

    float acc[2][8][4];

#pragma unroll 1
    for (int cc = 0; cc < 16; ++cc) {
        int layer = cc >> 3, c = cc & 7;
        asm volatile("cp.async.wait_group 2;" ::: "memory");
        __syncthreads();
        if (cc + 3 < 16) {
            int nx = cc + 3;
            stage_chunk16((const uint4*)(g_WTh +
                          (size_t)(((nx >> 3) * KSUB + k) * 8 + (nx & 7)) * 8192),
                          Wb + (nx & 3) * WBUF_HALVES, tid);
        } else {
            asm volatile("cp.async.commit_group;" ::: "memory");
        }
        if (c == 0) {
#pragma unroll
            for (int m = 0; m < 2; ++m)
#pragma unroll
                for (int nt = 0; nt < 8; ++nt)
#pragma unroll
                    for (int r = 0; r < 4; ++r) acc[m][nt][r] = 0.f;
        }
        unsigned wc = baseW + (unsigned)(cc & 3) * WBUF_BYTES;
        // f16-accumulator chains over this chunk's K=32, promoted to fp32 per m
#pragma unroll
        for (int m = 0; m < 2; ++m) {
            unsigned h0[8], h1[8];
#pragma unroll
            for (int nt = 0; nt < 8; ++nt) { h0[nt] = 0u; h1[nt] = 0u; }
#pragma unroll
            for (int ks = 0; ks < 2; ++ks) {
                int ka = c * 32 + ks * 16;
                unsigned a0, a1, a2, a3;
                unsigned addrA = baseA + offA_row +
                    (unsigned)((M0 + m * 16) * A_STRIDE + ka) * 2u;
                LDM_X4(a0, a1, a2, a3, addrA);
                unsigned br[16];
#pragma unroll
                for (int j = 0; j < 4; ++j) {
                    unsigned addrB = wc + offB_row +
                        (unsigned)((N0 + 16 * j) * W_STRIDE + ks * 16) * 2u;
                    LDM_X4(br[4 * j], br[4 * j + 1], br[4 * j + 2], br[4 * j + 3], addrB);
                }
#pragma unroll
                for (int nt = 0; nt < 8; ++nt)
                    HMMA16(h0[nt], h1[nt], a0, a1, a2, a3, br[2 * nt], br[2 * nt + 1]);
            }
#pragma unroll
            for (int nt = 0; nt < 8; ++nt) {
                float2 lo = __half22float2(*(__half2*)&h0[nt]);
                float2 hi = __half22float2(*(__half2*)&h1[nt]);
                acc[m][nt][0] += lo.x; acc[m][nt][1] += lo.y;
                acc[m][nt][2] += hi.x; acc[m][nt][3] += hi.y;
            }
        }
        if (c == 7) {   // layer done: bias + tanh -> back into A as fp16
            __syncthreads();
            const float* sb = sbias + layer * 256;
            int g = lane >> 2, t = lane & 3;
#pragma unroll
            for (int m = 0; m < 2; ++m) {
                int r0 = M0 + m * 16;
#pragma unroll
                for (int nt = 0; nt < 8; ++nt) {
                    int cb = N0 + nt * 8 + 2 * t;
                    float bx = sb[cb], by = sb[cb + 1];
                    __half2 v0 = __floats2half2_rn(ftanh(acc[m][nt][0] + bx),
                                                   ftanh(acc[m][nt][1] + by));
                    __half2 v1 = __floats2half2_rn(ftanh(acc[m][nt][2] + bx),
                                                   ftanh(acc[m][nt][3] + by));
                    *(__half2*)(A + (r0 + g) * A_STRIDE + cb) = v0;
                    *(__half2*)(A + (r0 + 8 + g) * A_STRIDE + cb) = v1;
                }
            }
        }
    }
    __syncthreads();

    // final: W3 dot + combine. thread = (point p, quarter s4 of 64 cols)
    {
        int p = tid >> 2, s4 = tid & 3;
        const __half2* Ar = (const __half2*)(A + p * A_STRIDE + s4 * 64);
        const float* w3 = sw3 + s4 * 64;
        float partial = 0.0f;
#pragma unroll 8
        for (int c2 = 0; c2 < 32; ++c2) {
            float2 v = __half22float2(Ar[c2]);
            partial = fmaf(v.x, w3[2 * c2], fmaf(v.y, w3[2 * c2 + 1], partial));
        }
        partial += __shfl_down_sync(0xffffffffu, partial, 2, 4);
        partial += __shfl_down_sync(0xffffffffu, partial, 1, 4);
        if (s4 == 0 && p < npts)
            atomicAdd(out + sidx[p], swn[p] * (partial + b3k));
    }
}

extern "C" void kernel_launch(void* const* d_in, const int* in_sizes, int n_in,
                              void* d_out, int out_size) {
    const float* x     = (const float*)d_in[0];
    const float* W0    = (const float*)d_in[1];
    const float* b0    = (const float*)d_in[2];
    const float* W1    = (const float*)d_in[3];
    const float* b1    = (const float*)d_in[4];
    const float* W2    = (const float*)d_in[5];
    const float* b2    = (const float*)d_in[6];
    const float* W3    = (const float*)d_in[7];
    const float* b3    = (const float*)d_in[8];
    const float* xmins = (const float*)d_in[9];
    const float* xmaxs = (const float*)d_in[10];
    float* out = (float*)d_out;

    cudaFuncSetAttribute(mlp_kernel,
                         cudaFuncAttributeMaxDynamicSharedMemorySize, SMEM_BYTES);

    prep_kernel<<<256, 256>>>(W1, W2);
    window_kernel<<<NPTS / 256, 256>>>(x, xmins, xmaxs, out);
    mlp_kernel<<<dim3(128, KSUB), NTHR, SMEM_BYTES>>>(
        x, W0, b0, b1, b2, W3, b3, xmins, xmaxs, out);
}